// round 14
// baseline (speedup 1.0000x reference)
#include <cuda_runtime.h>
#include <cuda_bf16.h>
#include <math.h>

// Problem constants
#define Bb 4
#define U1 2048
#define U2 2048
#define Cc 256
#define Ff 256
#define Mm 4
#define Dd 64

// ---------------- scratch (device globals: allocation-free) ----------------
__device__ float g_q[(long long)Bb * U1 * Cc];          // [B,U1,M*D]   8 MB
__device__ float g_k[(long long)Bb * U2 * Cc];          // [B,U2,M*D]   8 MB
__device__ float g_v[(long long)Bb * U2 * Mm * Ff];     // [B,U2,M*F]  32 MB
__device__ float g_s[(long long)Bb * Mm * U1 * U2];     // [B,M,U1,U2] 256 MB
__device__ float g_f[(long long)Bb * Mm * U1 * Ff];     // fused       32 MB
__device__ float g_m[(long long)Bb * Mm * U1 * Ff];     // mid         32 MB
__device__ float g_o[(long long)Bb * Mm * U1 * Ff];     // out (LN'd)  32 MB

// ---------------- tiled GEMM: C = A * B^T (NT), optional epilogue ----------
// A: [Mr,Kr] lda ; B: [Nr,Kr] ldb ; C: [Mr,Nr] ldc
// batch via blockIdx.z: z0 = z/zdiv, z1 = z%zdiv ; offsets z0*s?0 + z1*s?1
#define BM 64
#define BN 64
#define BK 16

template<bool BIAS, bool GELU_, bool SCLIP>
__global__ void gemm_nt(const float* __restrict__ A, const float* __restrict__ B,
                        const float* __restrict__ bias, float* __restrict__ C,
                        int Mr, int Nr, int Kr, int lda, int ldb, int ldc,
                        int zdiv,
                        long long sA0, long long sA1,
                        long long sB0, long long sB1,
                        long long sC0, long long sC1,
                        long long sBias1, float scale)
{
    int z  = blockIdx.z;
    int z0 = z / zdiv, z1 = z % zdiv;
    A += z0 * sA0 + z1 * sA1;
    B += z0 * sB0 + z1 * sB1;
    C += z0 * sC0 + z1 * sC1;
    if (BIAS) bias += z1 * sBias1;

    __shared__ float As[BK][BM + 4];
    __shared__ float Bs[BK][BN + 4];

    int tid = threadIdx.x;
    int tx = tid & 15, ty = tid >> 4;
    int row0 = blockIdx.y * BM;
    int col0 = blockIdx.x * BN;

    int lk = tid & 15;   // k within tile
    int li = tid >> 4;   // row/col within tile (step 16)

    float acc[4][4] = {};

    for (int k0 = 0; k0 < Kr; k0 += BK) {
        #pragma unroll
        for (int s = 0; s < 4; s++) {
            int i = li + s * 16;
            As[lk][i] = A[(long long)(row0 + i) * lda + k0 + lk];
            Bs[lk][i] = B[(long long)(col0 + i) * ldb + k0 + lk];
        }
        __syncthreads();
        #pragma unroll
        for (int kk = 0; kk < BK; kk++) {
            float4 a4 = *(const float4*)&As[kk][ty * 4];
            float4 b4 = *(const float4*)&Bs[kk][tx * 4];
            float a[4] = {a4.x, a4.y, a4.z, a4.w};
            float b[4] = {b4.x, b4.y, b4.z, b4.w};
            #pragma unroll
            for (int r = 0; r < 4; r++)
                #pragma unroll
                for (int c = 0; c < 4; c++)
                    acc[r][c] += a[r] * b[c];
        }
        __syncthreads();
    }

    #pragma unroll
    for (int r = 0; r < 4; r++) {
        int row = row0 + ty * 4 + r;
        #pragma unroll
        for (int c = 0; c < 4; c++) {
            int col = col0 + tx * 4 + c;
            float v = acc[r][c];
            if (SCLIP) { v *= scale; v = fminf(fmaxf(v, -500.f), 500.f); }
            if (BIAS)  v += bias[col];
            if (GELU_) v = 0.5f * v * (1.f + erff(v * 0.70710678118654752f));
            C[(long long)row * ldc + col] = v;
        }
    }
}

// ---------------- tiled GEMM: C = A * B (NN) --------------------------------
// A: [Mr,Kr] lda ; B: [Kr,Nr] ldb ; C: [Mr,Nr] ldc
__global__ void gemm_nn(const float* __restrict__ A, const float* __restrict__ B,
                        float* __restrict__ C,
                        int Mr, int Nr, int Kr, int lda, int ldb, int ldc,
                        int zdiv,
                        long long sA0, long long sA1,
                        long long sB0, long long sB1,
                        long long sC0, long long sC1)
{
    int z  = blockIdx.z;
    int z0 = z / zdiv, z1 = z % zdiv;
    A += z0 * sA0 + z1 * sA1;
    B += z0 * sB0 + z1 * sB1;
    C += z0 * sC0 + z1 * sC1;

    __shared__ float As[BK][BM + 4];
    __shared__ float Bs[BK][BN + 4];

    int tid = threadIdx.x;
    int tx = tid & 15, ty = tid >> 4;
    int row0 = blockIdx.y * BM;
    int col0 = blockIdx.x * BN;

    int lk  = tid & 15;
    int li  = tid >> 4;
    int lj  = tid & 63;
    int lkk = tid >> 6;

    float acc[4][4] = {};

    for (int k0 = 0; k0 < Kr; k0 += BK) {
        #pragma unroll
        for (int s = 0; s < 4; s++) {
            int i = li + s * 16;
            As[lk][i] = A[(long long)(row0 + i) * lda + k0 + lk];
        }
        #pragma unroll
        for (int s = 0; s < 4; s++) {
            int kk = lkk + s * 4;
            Bs[kk][lj] = B[(long long)(k0 + kk) * ldb + col0 + lj];
        }
        __syncthreads();
        #pragma unroll
        for (int kk = 0; kk < BK; kk++) {
            float4 a4 = *(const float4*)&As[kk][ty * 4];
            float4 b4 = *(const float4*)&Bs[kk][tx * 4];
            float a[4] = {a4.x, a4.y, a4.z, a4.w};
            float b[4] = {b4.x, b4.y, b4.z, b4.w};
            #pragma unroll
            for (int r = 0; r < 4; r++)
                #pragma unroll
                for (int c = 0; c < 4; c++)
                    acc[r][c] += a[r] * b[c];
        }
        __syncthreads();
    }

    #pragma unroll
    for (int r = 0; r < 4; r++) {
        int row = row0 + ty * 4 + r;
        #pragma unroll
        for (int c = 0; c < 4; c++) {
            int col = col0 + tx * 4 + c;
            C[(long long)row * ldc + col] = acc[r][c];
        }
    }
}

// ---------------- softmax over rows of length N (in place) ------------------
__global__ void softmax_rows(float* __restrict__ S, int N)
{
    float* row = S + (long long)blockIdx.x * N;
    __shared__ float red[256];
    int t = threadIdx.x;

    float m = -1e30f;
    for (int j = t; j < N; j += 256) m = fmaxf(m, row[j]);
    red[t] = m; __syncthreads();
    for (int s = 128; s > 0; s >>= 1) { if (t < s) red[t] = fmaxf(red[t], red[t + s]); __syncthreads(); }
    m = red[0]; __syncthreads();

    float sum = 0.f;
    for (int j = t; j < N; j += 256) { float e = __expf(row[j] - m); row[j] = e; sum += e; }
    red[t] = sum; __syncthreads();
    for (int s = 128; s > 0; s >>= 1) { if (t < s) red[t] += red[t + s]; __syncthreads(); }
    float inv = 1.f / red[0];

    for (int j = t; j < N; j += 256) row[j] *= inv;
}

// ---------------- layernorm over rows of length 256 (in place) --------------
__global__ void layernorm_rows(float* __restrict__ X,
                               const float* __restrict__ g, const float* __restrict__ b)
{
    float* row = X + (long long)blockIdx.x * 256;
    int t = threadIdx.x;
    float v = row[t];
    __shared__ float s1[256];

    s1[t] = v; __syncthreads();
    for (int s = 128; s > 0; s >>= 1) { if (t < s) s1[t] += s1[t + s]; __syncthreads(); }
    float mu = s1[0] * (1.f / 256.f);
    __syncthreads();

    float d = v - mu;
    s1[t] = d * d; __syncthreads();
    for (int s = 128; s > 0; s >>= 1) { if (t < s) s1[t] += s1[t + s]; __syncthreads(); }
    float var = s1[0] * (1.f / 256.f);

    row[t] = d * rsqrtf(var + 1e-12f) * g[t] + b[t];
}

// ---------------- learned soft aggregate over modes -------------------------
// O: [B,M,U1,F] (post-LN). For each (b,i): score_m = dot(O[b,m,i,:], ws) + b0,
// softmax over m, out[b,i,:] = sum_m p_m * O[b,m,i,:]
__global__ void aggregate_modes(const float* __restrict__ O, const float* __restrict__ ws,
                                const float* __restrict__ bsc, float* __restrict__ out)
{
    long long bi = blockIdx.x;
    int t = threadIdx.x;
    const float* base = O + (bi / U1) * (4LL * U1 * 256) + (bi % U1) * 256;

    float vals[4];
    float w = ws[t];
    __shared__ float red[4][256];
    #pragma unroll
    for (int m = 0; m < 4; m++) {
        vals[m] = base[(long long)m * U1 * 256 + t];
        red[m][t] = vals[m] * w;
    }
    __syncthreads();
    for (int s = 128; s > 0; s >>= 1) {
        if (t < s) {
            red[0][t] += red[0][t + s];
            red[1][t] += red[1][t + s];
            red[2][t] += red[2][t + s];
            red[3][t] += red[3][t + s];
        }
        __syncthreads();
    }
    float b0  = bsc[0];
    float sc0 = red[0][0] + b0, sc1 = red[1][0] + b0;
    float sc2 = red[2][0] + b0, sc3 = red[3][0] + b0;
    float mx  = fmaxf(fmaxf(sc0, sc1), fmaxf(sc2, sc3));
    float e0 = __expf(sc0 - mx), e1 = __expf(sc1 - mx);
    float e2 = __expf(sc2 - mx), e3 = __expf(sc3 - mx);
    float inv = 1.f / (e0 + e1 + e2 + e3);

    out[bi * 256 + t] = (vals[0] * e0 + vals[1] * e1 + vals[2] * e2 + vals[3] * e3) * inv;
}

// ---------------- host launcher ---------------------------------------------
extern "C" void kernel_launch(void* const* d_in, const int* in_sizes, int n_in,
                              void* d_out, int out_size)
{
    const float* qf  = (const float*)d_in[0];   // query_feat [B,U1,C]
    const float* kf  = (const float*)d_in[1];   // key_feat   [B,U2,C]
    const float* Wq  = (const float*)d_in[2];   // [M*D, C]
    const float* bq  = (const float*)d_in[3];   // [M*D]
    // d_in[4]=Wk, d_in[5]=bk : tied to Wq/bq (same values)
    const float* Wv  = (const float*)d_in[6];   // [M*F, C]
    const float* Wm  = (const float*)d_in[7];   // [F, F]
    const float* bm  = (const float*)d_in[8];   // [F]
    const float* Wo  = (const float*)d_in[9];   // [M, F, F]
    const float* bo  = (const float*)d_in[10];  // [M, F]
    const float* lng = (const float*)d_in[11];  // [F]
    const float* lnb = (const float*)d_in[12];  // [F]
    const float* Ws  = (const float*)d_in[13];  // [1, F]
    const float* bsc = (const float*)d_in[14];  // [1]
    float* out = (float*)d_out;                 // [B, U1, F]

    float *q, *k, *v, *s, *f, *mi, *o;
    cudaGetSymbolAddress((void**)&q,  g_q);
    cudaGetSymbolAddress((void**)&k,  g_k);
    cudaGetSymbolAddress((void**)&v,  g_v);
    cudaGetSymbolAddress((void**)&s,  g_s);
    cudaGetSymbolAddress((void**)&f,  g_f);
    cudaGetSymbolAddress((void**)&mi, g_m);
    cudaGetSymbolAddress((void**)&o,  g_o);

    dim3 blk(256);

    // q = query_feat @ Wq^T + bq   [B*U1=8192, 256] x [256, 256]
    gemm_nt<true, false, false><<<dim3(Cc / BN, (Bb * U1) / BM, 1), blk>>>(
        qf, Wq, bq, q, Bb * U1, Cc, Cc, Cc, Cc, Cc,
        1, 0, 0, 0, 0, 0, 0, 0, 1.f);

    // k = key_feat @ Wq^T + bq (tied weights)
    gemm_nt<true, false, false><<<dim3(Cc / BN, (Bb * U2) / BM, 1), blk>>>(
        kf, Wq, bq, k, Bb * U2, Cc, Cc, Cc, Cc, Cc,
        1, 0, 0, 0, 0, 0, 0, 0, 1.f);

    // v = key_feat @ Wv^T (no bias)   [8192, 256] x [1024, 256]^T
    gemm_nt<false, false, false><<<dim3((Mm * Ff) / BN, (Bb * U2) / BM, 1), blk>>>(
        kf, Wv, nullptr, v, Bb * U2, Mm * Ff, Cc, Cc, Cc, Mm * Ff,
        1, 0, 0, 0, 0, 0, 0, 0, 1.f);

    // scores[b,m] = q[b,:,m,:] @ k[b,:,m,:]^T / 8, clip +-500   (16 batched GEMMs, K=64)
    gemm_nt<false, false, true><<<dim3(U2 / BN, U1 / BM, Bb * Mm), blk>>>(
        q, k, nullptr, s, U1, U2, Dd, Cc, Cc, U2,
        Mm,
        (long long)U1 * Cc, Dd,                 // A offsets: b*U1*256 + m*64
        (long long)U2 * Cc, Dd,                 // B offsets: b*U2*256 + m*64
        (long long)Mm * U1 * U2, (long long)U1 * U2,
        0, 0.125f);

    // softmax over last dim (in place)
    softmax_rows<<<Bb * Mm * U1, 256>>>(s, U2);

    // fused[b,m] = probs[b,m] @ v[b,:,m,:]   (16 batched NN GEMMs, K=2048)
    gemm_nn<<<dim3(Ff / BN, U1 / BM, Bb * Mm), blk>>>(
        s, v, f, U1, Ff, U2, U2, Mm * Ff, Ff,
        Mm,
        (long long)Mm * U1 * U2, (long long)U1 * U2,
        (long long)U2 * Mm * Ff, Ff,
        (long long)Mm * U1 * Ff, (long long)U1 * Ff);

    // mid = gelu(fused @ W_mid^T + b_mid)   [32768, 256] x [256, 256]^T
    gemm_nt<true, true, false><<<dim3(Ff / BN, (Bb * Mm * U1) / BM, 1), blk>>>(
        f, Wm, bm, mi, Bb * Mm * U1, Ff, Ff, Ff, Ff, Ff,
        1, 0, 0, 0, 0, 0, 0, 0, 1.f);

    // out_pre[b,m] = mid[b,m] @ W_out[m]^T + b_out[m]
    gemm_nt<true, false, false><<<dim3(Ff / BN, U1 / BM, Bb * Mm), blk>>>(
        mi, Wo, bo, o, U1, Ff, Ff, Ff, Ff, Ff,
        Mm,
        (long long)Mm * U1 * Ff, (long long)U1 * Ff,
        0, (long long)Ff * Ff,
        (long long)Mm * U1 * Ff, (long long)U1 * Ff,
        Ff, 1.f);

    // layernorm (in place)
    layernorm_rows<<<Bb * Mm * U1, 256>>>(o, lng, lnb);

    // learned soft aggregate over modes
    aggregate_modes<<<Bb * U1, 256>>>(o, Ws, bsc, out);
}

// round 15
// speedup vs baseline: 1.0543x; 1.0543x over previous
#include <cuda_runtime.h>
#include <cuda_bf16.h>
#include <math.h>

// Problem constants
#define Bb 4
#define U1 2048
#define U2 2048
#define Cc 256
#define Ff 256
#define Mm 4
#define Dd 64

// ---------------- scratch (device globals: allocation-free) ----------------
__device__ float g_q[(long long)Bb * U1 * Cc];          // [B,U1,M*D]   8 MB
__device__ float g_k[(long long)Bb * U2 * Cc];          // [B,U2,M*D]   8 MB
__device__ float g_v[(long long)Bb * U2 * Mm * Ff];     // [B,U2,M*F]  32 MB
__device__ float g_s[(long long)Bb * Mm * U1 * U2];     // [B,M,U1,U2] 256 MB
__device__ float g_f[(long long)Bb * Mm * U1 * Ff];     // fused       32 MB
__device__ float g_m[(long long)Bb * Mm * U1 * Ff];     // mid         32 MB
__device__ float g_o[(long long)Bb * Mm * U1 * Ff];     // out (LN'd)  32 MB

// ---------------- tiled GEMM: C = A * B^T (NT), optional epilogue ----------
// A: [Mr,Kr] lda ; B: [Nr,Kr] ldb ; C: [Mr,Nr] ldc
// batch via blockIdx.z: z0 = z/zdiv, z1 = z%zdiv ; offsets z0*s?0 + z1*s?1
#define BM 64
#define BN 64
#define BK 16

template<bool BIAS, bool GELU_, bool SCLIP>
__global__ void gemm_nt(const float* __restrict__ A, const float* __restrict__ B,
                        const float* __restrict__ bias, float* __restrict__ C,
                        int Mr, int Nr, int Kr, int lda, int ldb, int ldc,
                        int zdiv,
                        long long sA0, long long sA1,
                        long long sB0, long long sB1,
                        long long sC0, long long sC1,
                        long long sBias1, float scale)
{
    int z  = blockIdx.z;
    int z0 = z / zdiv, z1 = z % zdiv;
    A += z0 * sA0 + z1 * sA1;
    B += z0 * sB0 + z1 * sB1;
    C += z0 * sC0 + z1 * sC1;
    if (BIAS) bias += z1 * sBias1;

    __shared__ float As[BK][BM + 4];
    __shared__ float Bs[BK][BN + 4];

    int tid = threadIdx.x;
    int tx = tid & 15, ty = tid >> 4;
    int row0 = blockIdx.y * BM;
    int col0 = blockIdx.x * BN;

    int lk = tid & 15;   // k within tile
    int li = tid >> 4;   // row/col within tile (step 16)

    float acc[4][4] = {};

    for (int k0 = 0; k0 < Kr; k0 += BK) {
        #pragma unroll
        for (int s = 0; s < 4; s++) {
            int i = li + s * 16;
            As[lk][i] = A[(long long)(row0 + i) * lda + k0 + lk];
            Bs[lk][i] = B[(long long)(col0 + i) * ldb + k0 + lk];
        }
        __syncthreads();
        #pragma unroll
        for (int kk = 0; kk < BK; kk++) {
            float4 a4 = *(const float4*)&As[kk][ty * 4];
            float4 b4 = *(const float4*)&Bs[kk][tx * 4];
            float a[4] = {a4.x, a4.y, a4.z, a4.w};
            float b[4] = {b4.x, b4.y, b4.z, b4.w};
            #pragma unroll
            for (int r = 0; r < 4; r++)
                #pragma unroll
                for (int c = 0; c < 4; c++)
                    acc[r][c] += a[r] * b[c];
        }
        __syncthreads();
    }

    #pragma unroll
    for (int r = 0; r < 4; r++) {
        int row = row0 + ty * 4 + r;
        #pragma unroll
        for (int c = 0; c < 4; c++) {
            int col = col0 + tx * 4 + c;
            float v = acc[r][c];
            if (SCLIP) { v *= scale; v = fminf(fmaxf(v, -500.f), 500.f); }
            if (BIAS)  v += bias[col];
            if (GELU_) v = 0.5f * v * (1.f + erff(v * 0.70710678118654752f));
            C[(long long)row * ldc + col] = v;
        }
    }
}

// ---------------- tiled GEMM: C = A * B (NN) --------------------------------
// A: [Mr,Kr] lda ; B: [Kr,Nr] ldb ; C: [Mr,Nr] ldc
__global__ void gemm_nn(const float* __restrict__ A, const float* __restrict__ B,
                        float* __restrict__ C,
                        int Mr, int Nr, int Kr, int lda, int ldb, int ldc,
                        int zdiv,
                        long long sA0, long long sA1,
                        long long sB0, long long sB1,
                        long long sC0, long long sC1)
{
    int z  = blockIdx.z;
    int z0 = z / zdiv, z1 = z % zdiv;
    A += z0 * sA0 + z1 * sA1;
    B += z0 * sB0 + z1 * sB1;
    C += z0 * sC0 + z1 * sC1;

    __shared__ float As[BK][BM + 4];
    __shared__ float Bs[BK][BN + 4];

    int tid = threadIdx.x;
    int tx = tid & 15, ty = tid >> 4;
    int row0 = blockIdx.y * BM;
    int col0 = blockIdx.x * BN;

    int lk  = tid & 15;
    int li  = tid >> 4;
    int lj  = tid & 63;
    int lkk = tid >> 6;

    float acc[4][4] = {};

    for (int k0 = 0; k0 < Kr; k0 += BK) {
        #pragma unroll
        for (int s = 0; s < 4; s++) {
            int i = li + s * 16;
            As[lk][i] = A[(long long)(row0 + i) * lda + k0 + lk];
        }
        #pragma unroll
        for (int s = 0; s < 4; s++) {
            int kk = lkk + s * 4;
            Bs[kk][lj] = B[(long long)(k0 + kk) * ldb + col0 + lj];
        }
        __syncthreads();
        #pragma unroll
        for (int kk = 0; kk < BK; kk++) {
            float4 a4 = *(const float4*)&As[kk][ty * 4];
            float4 b4 = *(const float4*)&Bs[kk][tx * 4];
            float a[4] = {a4.x, a4.y, a4.z, a4.w};
            float b[4] = {b4.x, b4.y, b4.z, b4.w};
            #pragma unroll
            for (int r = 0; r < 4; r++)
                #pragma unroll
                for (int c = 0; c < 4; c++)
                    acc[r][c] += a[r] * b[c];
        }
        __syncthreads();
    }

    #pragma unroll
    for (int r = 0; r < 4; r++) {
        int row = row0 + ty * 4 + r;
        #pragma unroll
        for (int c = 0; c < 4; c++) {
            int col = col0 + tx * 4 + c;
            C[(long long)row * ldc + col] = acc[r][c];
        }
    }
}

// ---------------- softmax over rows of length N (in place) ------------------
__global__ void softmax_rows(float* __restrict__ S, int N)
{
    float* row = S + (long long)blockIdx.x * N;
    __shared__ float red[256];
    int t = threadIdx.x;

    float m = -1e30f;
    for (int j = t; j < N; j += 256) m = fmaxf(m, row[j]);
    red[t] = m; __syncthreads();
    for (int s = 128; s > 0; s >>= 1) { if (t < s) red[t] = fmaxf(red[t], red[t + s]); __syncthreads(); }
    m = red[0]; __syncthreads();

    float sum = 0.f;
    for (int j = t; j < N; j += 256) { float e = __expf(row[j] - m); row[j] = e; sum += e; }
    red[t] = sum; __syncthreads();
    for (int s = 128; s > 0; s >>= 1) { if (t < s) red[t] += red[t + s]; __syncthreads(); }
    float inv = 1.f / red[0];

    for (int j = t; j < N; j += 256) row[j] *= inv;
}

// ---------------- layernorm over rows of length 256 (in place) --------------
__global__ void layernorm_rows(float* __restrict__ X,
                               const float* __restrict__ g, const float* __restrict__ b)
{
    float* row = X + (long long)blockIdx.x * 256;
    int t = threadIdx.x;
    float v = row[t];
    __shared__ float s1[256];

    s1[t] = v; __syncthreads();
    for (int s = 128; s > 0; s >>= 1) { if (t < s) s1[t] += s1[t + s]; __syncthreads(); }
    float mu = s1[0] * (1.f / 256.f);
    __syncthreads();

    float d = v - mu;
    s1[t] = d * d; __syncthreads();
    for (int s = 128; s > 0; s >>= 1) { if (t < s) s1[t] += s1[t + s]; __syncthreads(); }
    float var = s1[0] * (1.f / 256.f);

    row[t] = d * rsqrtf(var + 1e-12f) * g[t] + b[t];
}

// ---------------- learned soft aggregate over modes -------------------------
// O: [B,M,U1,F] (post-LN). For each (b,i): score_m = dot(O[b,m,i,:], ws) + b0,
// softmax over m, out[b,i,:] = sum_m p_m * O[b,m,i,:]
__global__ void aggregate_modes(const float* __restrict__ O, const float* __restrict__ ws,
                                const float* __restrict__ bsc, float* __restrict__ out)
{
    long long bi = blockIdx.x;
    int t = threadIdx.x;
    const float* base = O + (bi / U1) * (4LL * U1 * 256) + (bi % U1) * 256;

    float vals[4];
    float w = ws[t];
    __shared__ float red[4][256];
    #pragma unroll
    for (int m = 0; m < 4; m++) {
        vals[m] = base[(long long)m * U1 * 256 + t];
        red[m][t] = vals[m] * w;
    }
    __syncthreads();
    for (int s = 128; s > 0; s >>= 1) {
        if (t < s) {
            red[0][t] += red[0][t + s];
            red[1][t] += red[1][t + s];
            red[2][t] += red[2][t + s];
            red[3][t] += red[3][t + s];
        }
        __syncthreads();
    }
    float b0  = bsc[0];
    float sc0 = red[0][0] + b0, sc1 = red[1][0] + b0;
    float sc2 = red[2][0] + b0, sc3 = red[3][0] + b0;
    float mx  = fmaxf(fmaxf(sc0, sc1), fmaxf(sc2, sc3));
    float e0 = __expf(sc0 - mx), e1 = __expf(sc1 - mx);
    float e2 = __expf(sc2 - mx), e3 = __expf(sc3 - mx);
    float inv = 1.f / (e0 + e1 + e2 + e3);

    out[bi * 256 + t] = (vals[0] * e0 + vals[1] * e1 + vals[2] * e2 + vals[3] * e3) * inv;
}

// ---------------- host launcher ---------------------------------------------
extern "C" void kernel_launch(void* const* d_in, const int* in_sizes, int n_in,
                              void* d_out, int out_size)
{
    const float* qf  = (const float*)d_in[0];   // query_feat [B,U1,C]
    const float* kf  = (const float*)d_in[1];   // key_feat   [B,U2,C]
    const float* Wq  = (const float*)d_in[2];   // [M*D, C]
    const float* bq  = (const float*)d_in[3];   // [M*D]
    // d_in[4]=Wk, d_in[5]=bk : tied to Wq/bq (same values)
    const float* Wv  = (const float*)d_in[6];   // [M*F, C]
    const float* Wm  = (const float*)d_in[7];   // [F, F]
    const float* bm  = (const float*)d_in[8];   // [F]
    const float* Wo  = (const float*)d_in[9];   // [M, F, F]
    const float* bo  = (const float*)d_in[10];  // [M, F]
    const float* lng = (const float*)d_in[11];  // [F]
    const float* lnb = (const float*)d_in[12];  // [F]
    const float* Ws  = (const float*)d_in[13];  // [1, F]
    const float* bsc = (const float*)d_in[14];  // [1]
    float* out = (float*)d_out;                 // [B, U1, F]

    float *q, *k, *v, *s, *f, *mi, *o;
    cudaGetSymbolAddress((void**)&q,  g_q);
    cudaGetSymbolAddress((void**)&k,  g_k);
    cudaGetSymbolAddress((void**)&v,  g_v);
    cudaGetSymbolAddress((void**)&s,  g_s);
    cudaGetSymbolAddress((void**)&f,  g_f);
    cudaGetSymbolAddress((void**)&mi, g_m);
    cudaGetSymbolAddress((void**)&o,  g_o);

    dim3 blk(256);

    // q = query_feat @ Wq^T + bq   [B*U1=8192, 256] x [256, 256]
    gemm_nt<true, false, false><<<dim3(Cc / BN, (Bb * U1) / BM, 1), blk>>>(
        qf, Wq, bq, q, Bb * U1, Cc, Cc, Cc, Cc, Cc,
        1, 0, 0, 0, 0, 0, 0, 0, 1.f);

    // k = key_feat @ Wq^T + bq (tied weights)
    gemm_nt<true, false, false><<<dim3(Cc / BN, (Bb * U2) / BM, 1), blk>>>(
        kf, Wq, bq, k, Bb * U2, Cc, Cc, Cc, Cc, Cc,
        1, 0, 0, 0, 0, 0, 0, 0, 1.f);

    // v = key_feat @ Wv^T (no bias)   [8192, 256] x [1024, 256]^T
    gemm_nt<false, false, false><<<dim3((Mm * Ff) / BN, (Bb * U2) / BM, 1), blk>>>(
        kf, Wv, nullptr, v, Bb * U2, Mm * Ff, Cc, Cc, Cc, Mm * Ff,
        1, 0, 0, 0, 0, 0, 0, 0, 1.f);

    // scores[b,m] = q[b,:,m,:] @ k[b,:,m,:]^T / 8, clip +-500   (16 batched GEMMs, K=64)
    gemm_nt<false, false, true><<<dim3(U2 / BN, U1 / BM, Bb * Mm), blk>>>(
        q, k, nullptr, s, U1, U2, Dd, Cc, Cc, U2,
        Mm,
        (long long)U1 * Cc, Dd,                 // A offsets: b*U1*256 + m*64
        (long long)U2 * Cc, Dd,                 // B offsets: b*U2*256 + m*64
        (long long)Mm * U1 * U2, (long long)U1 * U2,
        0, 0.125f);

    // softmax over last dim (in place)
    softmax_rows<<<Bb * Mm * U1, 256>>>(s, U2);

    // fused[b,m] = probs[b,m] @ v[b,:,m,:]   (16 batched NN GEMMs, K=2048)
    gemm_nn<<<dim3(Ff / BN, U1 / BM, Bb * Mm), blk>>>(
        s, v, f, U1, Ff, U2, U2, Mm * Ff, Ff,
        Mm,
        (long long)Mm * U1 * U2, (long long)U1 * U2,
        (long long)U2 * Mm * Ff, Ff,
        (long long)Mm * U1 * Ff, (long long)U1 * Ff);

    // mid = gelu(fused @ W_mid^T + b_mid)   [32768, 256] x [256, 256]^T
    gemm_nt<true, true, false><<<dim3(Ff / BN, (Bb * Mm * U1) / BM, 1), blk>>>(
        f, Wm, bm, mi, Bb * Mm * U1, Ff, Ff, Ff, Ff, Ff,
        1, 0, 0, 0, 0, 0, 0, 0, 1.f);

    // out_pre[b,m] = mid[b,m] @ W_out[m]^T + b_out[m]
    gemm_nt<true, false, false><<<dim3(Ff / BN, U1 / BM, Bb * Mm), blk>>>(
        mi, Wo, bo, o, U1, Ff, Ff, Ff, Ff, Ff,
        Mm,
        (long long)Mm * U1 * Ff, (long long)U1 * Ff,
        0, (long long)Ff * Ff,
        (long long)Mm * U1 * Ff, (long long)U1 * Ff,
        Ff, 1.f);

    // layernorm (in place)
    layernorm_rows<<<Bb * Mm * U1, 256>>>(o, lng, lnb);

    // learned soft aggregate over modes
    aggregate_modes<<<Bb * U1, 256>>>(o, Ws, bsc, out);
}